// round 2
// baseline (speedup 1.0000x reference)
#include <cuda_runtime.h>

#define IN_C 64
#define OUT_C 16
#define EA_D 8
#define NMAX 100000

// scratch: h = x @ lin_w + lin_b  [N, 16]
__device__ __align__(16) float g_h[NMAX * OUT_C];
// piecewise-linear representation of the attn MLP scalar function
__device__ float g_bp[16];     // sorted breakpoints
__device__ float2 g_AB[17];    // per-interval (A, B): f(t) = A*t + B

// ---------------------------------------------------------------------------
// Setup: build piecewise-linear tables for
//   f(t) = sum_j relu(t*w1[j] + b1[j]) * w2[j] + b2
// ---------------------------------------------------------------------------
__global__ void setup_kernel(const float* __restrict__ w1, const float* __restrict__ b1,
                             const float* __restrict__ w2, const float* __restrict__ b2) {
    if (threadIdx.x != 0 || blockIdx.x != 0) return;
    float W1[16], B1[16], W2[16], r[16];
    for (int j = 0; j < 16; j++) { W1[j] = w1[j]; B1[j] = b1[j]; W2[j] = w2[j]; }
    for (int j = 0; j < 16; j++) {
        float w = W1[j];
        float v;
        if (w == 0.0f) {
            v = 1e30f;                      // never crossed for realistic t
        } else {
            v = -B1[j] / w;
            v = fminf(fmaxf(v, -1e30f), 1e30f);
            if (!(v == v)) v = 1e30f;       // NaN guard
        }
        r[j] = v;
    }
    // insertion sort (16 elements)
    for (int i = 1; i < 16; i++) {
        float v = r[i];
        int k = i - 1;
        while (k >= 0 && r[k] > v) { r[k + 1] = r[k]; k--; }
        r[k + 1] = v;
    }
    for (int j = 0; j < 16; j++) g_bp[j] = r[j];
    float b2v = b2[0];
    for (int k = 0; k <= 16; k++) {
        // pick a test point strictly inside interval k
        float tp;
        if (k == 0)       tp = r[0] - 1.0f;
        else if (k == 16) tp = r[15] + 1.0f;
        else              tp = 0.5f * r[k - 1] + 0.5f * r[k];
        float A = 0.0f, B = b2v;
        for (int j = 0; j < 16; j++) {
            float v = tp * W1[j] + B1[j];
            if (v > 0.0f) { A += W1[j] * W2[j]; B += B1[j] * W2[j]; }
        }
        g_AB[k] = make_float2(A, B);
    }
}

// ---------------------------------------------------------------------------
// h = x @ lin_w + lin_b   (thread per node, weights in shared)
// ---------------------------------------------------------------------------
__global__ void h_kernel(const float* __restrict__ x, const float* __restrict__ lw,
                         const float* __restrict__ lb, int n) {
    __shared__ float ws[IN_C * OUT_C];
    __shared__ float bs[OUT_C];
    for (int i = threadIdx.x; i < IN_C * OUT_C; i += blockDim.x) ws[i] = lw[i];
    if (threadIdx.x < OUT_C) bs[threadIdx.x] = lb[threadIdx.x];
    __syncthreads();
    int n0 = blockIdx.x * blockDim.x + threadIdx.x;
    if (n0 >= n) return;
    const float4* xr = (const float4*)(x + (size_t)n0 * IN_C);
    float acc[OUT_C];
#pragma unroll
    for (int c = 0; c < OUT_C; c++) acc[c] = bs[c];
#pragma unroll 4
    for (int k4 = 0; k4 < IN_C / 4; k4++) {
        float4 xv = xr[k4];
#pragma unroll
        for (int c = 0; c < OUT_C; c++) {
            acc[c] = fmaf(xv.x, ws[(k4 * 4 + 0) * OUT_C + c], acc[c]);
            acc[c] = fmaf(xv.y, ws[(k4 * 4 + 1) * OUT_C + c], acc[c]);
            acc[c] = fmaf(xv.z, ws[(k4 * 4 + 2) * OUT_C + c], acc[c]);
            acc[c] = fmaf(xv.w, ws[(k4 * 4 + 3) * OUT_C + c], acc[c]);
        }
    }
    float4* ho = (float4*)(g_h + (size_t)n0 * OUT_C);
    ho[0] = make_float4(acc[0], acc[1], acc[2], acc[3]);
    ho[1] = make_float4(acc[4], acc[5], acc[6], acc[7]);
    ho[2] = make_float4(acc[8], acc[9], acc[10], acc[11]);
    ho[3] = make_float4(acc[12], acc[13], acc[14], acc[15]);
}

// ---------------------------------------------------------------------------
// Edge kernel: ea GEMV + gather + piecewise-linear attn MLP + softmax + scatter
// ---------------------------------------------------------------------------
__global__ void edge_kernel(const int* __restrict__ ei, const float* __restrict__ eattr,
                            const float* __restrict__ eaw, const float* __restrict__ eab,
                            float* __restrict__ out, int E) {
    __shared__ float sw[EA_D * OUT_C];
    __shared__ float sb[OUT_C];
    __shared__ float sbp[16];
    __shared__ float2 sAB[17];
    int t = threadIdx.x;
    if (t < EA_D * OUT_C) sw[t] = eaw[t];
    if (t < OUT_C) sb[t] = eab[t];
    if (t >= 128 && t < 144) sbp[t - 128] = g_bp[t - 128];
    if (t >= 160 && t < 177) sAB[t - 160] = g_AB[t - 160];
    __syncthreads();

    int e = blockIdx.x * blockDim.x + t;
    if (e >= E) return;

    int row = ei[e] - 1;       // edge_index[0] - 1
    int col = ei[E + e];       // edge_index[1]

    const float4* ap = (const float4*)(eattr + (size_t)e * EA_D);
    float4 a0 = ap[0], a1 = ap[1];
    float av[8] = {a0.x, a0.y, a0.z, a0.w, a1.x, a1.y, a1.z, a1.w};

    const float4* hp = (const float4*)(g_h + (size_t)col * OUT_C);
    float4 h0 = hp[0], h1 = hp[1], h2 = hp[2], h3 = hp[3];
    float hv[16] = {h0.x, h0.y, h0.z, h0.w, h1.x, h1.y, h1.z, h1.w,
                    h2.x, h2.y, h2.z, h2.w, h3.x, h3.y, h3.z, h3.w};

    float agg[16];
#pragma unroll
    for (int c = 0; c < OUT_C; c++) {
        float s = sb[c];
#pragma unroll
        for (int k = 0; k < EA_D; k++) s = fmaf(av[k], sw[k * OUT_C + c], s);
        agg[c] = hv[c] * s;
    }

    // scores via piecewise-linear lookup: 4-step binary search over sorted bps
    float sc[16];
#pragma unroll
    for (int c = 0; c < OUT_C; c++) {
        float tv = agg[c];
        int p = (tv >= sbp[7]) ? 8 : 0;
        p += (tv >= sbp[p + 3]) ? 4 : 0;
        p += (tv >= sbp[p + 1]) ? 2 : 0;
        p += (tv >= sbp[p]) ? 1 : 0;
        float2 ab = sAB[p];
        sc[c] = fmaf(ab.x, tv, ab.y);
    }

    // softmax over 16 channels
    float m = sc[0];
#pragma unroll
    for (int c = 1; c < OUT_C; c++) m = fmaxf(m, sc[c]);
    float sum = 0.0f;
#pragma unroll
    for (int c = 0; c < OUT_C; c++) { sc[c] = __expf(sc[c] - m); sum += sc[c]; }
    float inv = 1.0f / sum;

    float* op = out + (size_t)row * OUT_C;
#pragma unroll
    for (int c4 = 0; c4 < 4; c4++) {
        float v0 = agg[c4 * 4 + 0] * sc[c4 * 4 + 0] * inv;
        float v1 = agg[c4 * 4 + 1] * sc[c4 * 4 + 1] * inv;
        float v2 = agg[c4 * 4 + 2] * sc[c4 * 4 + 2] * inv;
        float v3 = agg[c4 * 4 + 3] * sc[c4 * 4 + 3] * inv;
        asm volatile("red.global.add.v4.f32 [%0], {%1, %2, %3, %4};"
                     :: "l"(op + c4 * 4), "f"(v0), "f"(v1), "f"(v2), "f"(v3)
                     : "memory");
    }
}

// ---------------------------------------------------------------------------
extern "C" void kernel_launch(void* const* d_in, const int* in_sizes, int n_in,
                              void* d_out, int out_size) {
    const float* x     = (const float*)d_in[0];
    const int*   ei    = (const int*)  d_in[1];
    const float* eattr = (const float*)d_in[2];
    const float* lw    = (const float*)d_in[3];
    const float* lb    = (const float*)d_in[4];
    const float* eaw   = (const float*)d_in[5];
    const float* eab   = (const float*)d_in[6];
    const float* aw1   = (const float*)d_in[7];
    const float* ab1   = (const float*)d_in[8];
    const float* aw2   = (const float*)d_in[9];
    const float* ab2   = (const float*)d_in[10];
    float* out = (float*)d_out;

    int n = in_sizes[0] / IN_C;
    int E = in_sizes[2] / EA_D;

    cudaMemsetAsync(out, 0, (size_t)out_size * sizeof(float));
    setup_kernel<<<1, 32>>>(aw1, ab1, aw2, ab2);
    h_kernel<<<(n + 127) / 128, 128>>>(x, lw, lb, n);
    edge_kernel<<<(E + 255) / 256, 256>>>(ei, eattr, eaw, eab, out, E);
}

// round 3
// speedup vs baseline: 1.0976x; 1.0976x over previous
#include <cuda_runtime.h>

#define IN_C 64
#define OUT_C 16
#define EA_D 8

// scratch: h = x @ lin_w + lin_b  [N, 16]
__device__ __align__(16) float g_h[100000 * OUT_C];

// ---------------------------------------------------------------------------
// h = x @ lin_w + lin_b   (thread per node, weights in shared)
// also zeroes the output buffer (same [N,16] shape), replacing cudaMemset.
// ---------------------------------------------------------------------------
__global__ void h_kernel(const float* __restrict__ x, const float* __restrict__ lw,
                         const float* __restrict__ lb, float* __restrict__ out, int n) {
    __shared__ float ws[IN_C * OUT_C];
    __shared__ float bs[OUT_C];
    for (int i = threadIdx.x; i < IN_C * OUT_C; i += blockDim.x) ws[i] = lw[i];
    if (threadIdx.x < OUT_C) bs[threadIdx.x] = lb[threadIdx.x];
    __syncthreads();
    int n0 = blockIdx.x * blockDim.x + threadIdx.x;
    if (n0 >= n) return;

    // zero output row (replaces cudaMemsetAsync launch)
    float4 z = make_float4(0.f, 0.f, 0.f, 0.f);
    float4* orow = (float4*)(out + (size_t)n0 * OUT_C);
    orow[0] = z; orow[1] = z; orow[2] = z; orow[3] = z;

    const float4* xr = (const float4*)(x + (size_t)n0 * IN_C);
    float acc[OUT_C];
#pragma unroll
    for (int c = 0; c < OUT_C; c++) acc[c] = bs[c];
#pragma unroll 4
    for (int k4 = 0; k4 < IN_C / 4; k4++) {
        float4 xv = xr[k4];
#pragma unroll
        for (int c = 0; c < OUT_C; c++) {
            acc[c] = fmaf(xv.x, ws[(k4 * 4 + 0) * OUT_C + c], acc[c]);
            acc[c] = fmaf(xv.y, ws[(k4 * 4 + 1) * OUT_C + c], acc[c]);
            acc[c] = fmaf(xv.z, ws[(k4 * 4 + 2) * OUT_C + c], acc[c]);
            acc[c] = fmaf(xv.w, ws[(k4 * 4 + 3) * OUT_C + c], acc[c]);
        }
    }
    float4* ho = (float4*)(g_h + (size_t)n0 * OUT_C);
    ho[0] = make_float4(acc[0], acc[1], acc[2], acc[3]);
    ho[1] = make_float4(acc[4], acc[5], acc[6], acc[7]);
    ho[2] = make_float4(acc[8], acc[9], acc[10], acc[11]);
    ho[3] = make_float4(acc[12], acc[13], acc[14], acc[15]);
}

// ---------------------------------------------------------------------------
// Edge kernel: per-block inline pwl-table construction, then
// ea GEMV + gather + piecewise-linear attn MLP + softmax + scatter-add.
//
// The attn MLP  f(t) = sum_j relu(t*w1[j]+b1[j])*w2[j] + b2  is a scalar
// piecewise-linear function with 16 breakpoints; we build the sorted
// breakpoints + per-interval (A,B) in shared at block start (~400 cyc,
// overlapped across blocks), then each score is a 4-step search + 1 FMA.
// ---------------------------------------------------------------------------
__global__ void edge_kernel(const int* __restrict__ ei, const float* __restrict__ eattr,
                            const float* __restrict__ eaw, const float* __restrict__ eab,
                            const float* __restrict__ w1, const float* __restrict__ b1,
                            const float* __restrict__ w2, const float* __restrict__ b2,
                            float* __restrict__ out, int E) {
    __shared__ float sw[EA_D * OUT_C];
    __shared__ float sb[OUT_C];
    __shared__ float raw[16];      // unsorted breakpoints
    __shared__ float sbp[16];      // sorted breakpoints
    __shared__ float2 sAB[17];     // per-interval (A,B): f(t) = A*t + B
    int t = threadIdx.x;

    if (t < EA_D * OUT_C) sw[t] = eaw[t];
    if (t < OUT_C) sb[t] = eab[t];

    // phase 1: raw breakpoints (threads 0..15)
    if (t < 16) {
        float w = w1[t];
        float v;
        if (w == 0.0f) {
            v = 1e30f;
        } else {
            v = -b1[t] / w;
            v = fminf(fmaxf(v, -1e30f), 1e30f);
            if (!(v == v)) v = 1e30f;
        }
        raw[t] = v;
    }
    __syncthreads();

    // phase 2: rank-sort (threads 0..15)
    if (t < 16) {
        float v = raw[t];
        int rank = 0;
#pragma unroll
        for (int k = 0; k < 16; k++) {
            float u = raw[k];
            rank += (u < v) || (u == v && k < t);
        }
        sbp[rank] = v;
    }
    __syncthreads();

    // phase 3: per-interval (A,B) via test points (threads 0..16)
    if (t <= 16) {
        float tp;
        if (t == 0)       tp = sbp[0] - 1.0f;
        else if (t == 16) tp = sbp[15] + 1.0f;
        else              tp = 0.5f * sbp[t - 1] + 0.5f * sbp[t];
        float A = 0.0f, B = b2[0];
#pragma unroll
        for (int j = 0; j < 16; j++) {
            float wj = w1[j], bj = b1[j];
            float v = tp * wj + bj;
            if (v > 0.0f) { A += wj * w2[j]; B += bj * w2[j]; }
        }
        sAB[t] = make_float2(A, B);
    }
    __syncthreads();

    int e = blockIdx.x * blockDim.x + t;
    if (e >= E) return;

    int row = ei[e] - 1;       // edge_index[0] - 1
    int col = ei[E + e];       // edge_index[1]

    const float4* ap = (const float4*)(eattr + (size_t)e * EA_D);
    float4 a0 = ap[0], a1 = ap[1];
    float av[8] = {a0.x, a0.y, a0.z, a0.w, a1.x, a1.y, a1.z, a1.w};

    const float4* hp = (const float4*)(g_h + (size_t)col * OUT_C);
    float4 h0 = hp[0], h1 = hp[1], h2 = hp[2], h3 = hp[3];
    float hv[16] = {h0.x, h0.y, h0.z, h0.w, h1.x, h1.y, h1.z, h1.w,
                    h2.x, h2.y, h2.z, h2.w, h3.x, h3.y, h3.z, h3.w};

    float agg[16];
#pragma unroll
    for (int c = 0; c < OUT_C; c++) {
        float s = sb[c];
#pragma unroll
        for (int k = 0; k < EA_D; k++) s = fmaf(av[k], sw[k * OUT_C + c], s);
        agg[c] = hv[c] * s;
    }

    // scores via piecewise-linear lookup: 4-step binary search over sorted bps
    float sc[16];
#pragma unroll
    for (int c = 0; c < OUT_C; c++) {
        float tv = agg[c];
        int p = (tv >= sbp[7]) ? 8 : 0;
        p += (tv >= sbp[p + 3]) ? 4 : 0;
        p += (tv >= sbp[p + 1]) ? 2 : 0;
        p += (tv >= sbp[p]) ? 1 : 0;
        float2 ab = sAB[p];
        sc[c] = fmaf(ab.x, tv, ab.y);
    }

    // softmax over 16 channels
    float m = sc[0];
#pragma unroll
    for (int c = 1; c < OUT_C; c++) m = fmaxf(m, sc[c]);
    float sum = 0.0f;
#pragma unroll
    for (int c = 0; c < OUT_C; c++) { sc[c] = __expf(sc[c] - m); sum += sc[c]; }
    float inv = 1.0f / sum;

    float* op = out + (size_t)row * OUT_C;
#pragma unroll
    for (int c4 = 0; c4 < 4; c4++) {
        float v0 = agg[c4 * 4 + 0] * sc[c4 * 4 + 0] * inv;
        float v1 = agg[c4 * 4 + 1] * sc[c4 * 4 + 1] * inv;
        float v2 = agg[c4 * 4 + 2] * sc[c4 * 4 + 2] * inv;
        float v3 = agg[c4 * 4 + 3] * sc[c4 * 4 + 3] * inv;
        asm volatile("red.global.add.v4.f32 [%0], {%1, %2, %3, %4};"
                     :: "l"(op + c4 * 4), "f"(v0), "f"(v1), "f"(v2), "f"(v3)
                     : "memory");
    }
}

// ---------------------------------------------------------------------------
extern "C" void kernel_launch(void* const* d_in, const int* in_sizes, int n_in,
                              void* d_out, int out_size) {
    const float* x     = (const float*)d_in[0];
    const int*   ei    = (const int*)  d_in[1];
    const float* eattr = (const float*)d_in[2];
    const float* lw    = (const float*)d_in[3];
    const float* lb    = (const float*)d_in[4];
    const float* eaw   = (const float*)d_in[5];
    const float* eab   = (const float*)d_in[6];
    const float* aw1   = (const float*)d_in[7];
    const float* ab1   = (const float*)d_in[8];
    const float* aw2   = (const float*)d_in[9];
    const float* ab2   = (const float*)d_in[10];
    float* out = (float*)d_out;

    int n = in_sizes[0] / IN_C;
    int E = in_sizes[2] / EA_D;

    h_kernel<<<(n + 255) / 256, 256>>>(x, lw, lb, out, n);
    edge_kernel<<<(E + 255) / 256, 256>>>(ei, eattr, eaw, eab,
                                          aw1, ab1, aw2, ab2, out, E);
}

// round 4
// speedup vs baseline: 1.1800x; 1.0751x over previous
#include <cuda_runtime.h>

#define IN_C 64
#define OUT_C 16
#define EA_D 8

// scratch: h = x @ lin_w + lin_b  [N, 16]
__device__ __align__(16) float g_h[100000 * OUT_C];
// piecewise-linear representation of the attn MLP scalar function
__device__ float g_bp[16];                 // sorted breakpoints
__device__ __align__(8) float2 g_AB[17];   // per-interval (A,B): f(t)=A*t+B

// ---------------------------------------------------------------------------
// h = x @ lin_w + lin_b (thread/node, weights in shared, float4 LDS).
// Also zeroes out[] and (block 0) builds the pwl tables for the attn MLP.
// ---------------------------------------------------------------------------
__global__ void h_kernel(const float* __restrict__ x, const float* __restrict__ lw,
                         const float* __restrict__ lb, float* __restrict__ out,
                         const float* __restrict__ w1, const float* __restrict__ b1,
                         const float* __restrict__ w2, const float* __restrict__ b2,
                         int n) {
    __shared__ __align__(16) float ws[IN_C * OUT_C];
    __shared__ float bs[OUT_C];
    __shared__ float raw[16];
    __shared__ float srt[16];
    int t = threadIdx.x;
    for (int i = t; i < IN_C * OUT_C; i += blockDim.x) ws[i] = lw[i];
    if (t < OUT_C) bs[t] = lb[t];

    // ---- block 0: build pwl tables for f(t)=sum relu(t*w1+b1)*w2 + b2 ----
    if (blockIdx.x == 0 && t < 16) {
        float w = w1[t];
        float v;
        if (w == 0.0f) v = 1e30f;
        else {
            v = -b1[t] / w;
            v = fminf(fmaxf(v, -1e30f), 1e30f);
            if (!(v == v)) v = 1e30f;
        }
        raw[t] = v;
    }
    __syncthreads();
    if (blockIdx.x == 0 && t < 16) {
        float v = raw[t];
        int rank = 0;
#pragma unroll
        for (int k = 0; k < 16; k++) {
            float u = raw[k];
            rank += (u < v) || (u == v && k < t);
        }
        srt[rank] = v;
    }
    __syncthreads();
    if (blockIdx.x == 0 && t <= 16) {
        if (t < 16) g_bp[t] = srt[t];
        float tp;
        if (t == 0)       tp = srt[0] - 1.0f;
        else if (t == 16) tp = srt[15] + 1.0f;
        else              tp = 0.5f * srt[t - 1] + 0.5f * srt[t];
        float A = 0.0f, B = b2[0];
#pragma unroll
        for (int j = 0; j < 16; j++) {
            float wj = w1[j], bj = b1[j];
            float v = tp * wj + bj;
            if (v > 0.0f) { A += wj * w2[j]; B += bj * w2[j]; }
        }
        g_AB[t] = make_float2(A, B);
    }

    int n0 = blockIdx.x * blockDim.x + t;
    if (n0 >= n) return;

    // zero output row (replaces cudaMemsetAsync launch)
    float4 z = make_float4(0.f, 0.f, 0.f, 0.f);
    float4* orow = (float4*)(out + (size_t)n0 * OUT_C);
    orow[0] = z; orow[1] = z; orow[2] = z; orow[3] = z;

    const float4* xr = (const float4*)(x + (size_t)n0 * IN_C);
    float acc[OUT_C];
#pragma unroll
    for (int c = 0; c < OUT_C; c++) acc[c] = bs[c];
#pragma unroll 4
    for (int k4 = 0; k4 < IN_C / 4; k4++) {
        float4 xv = xr[k4];
        float xs[4] = {xv.x, xv.y, xv.z, xv.w};
#pragma unroll
        for (int kk = 0; kk < 4; kk++) {
            int k = k4 * 4 + kk;
#pragma unroll
            for (int c4 = 0; c4 < 4; c4++) {
                float4 w = *(const float4*)&ws[k * OUT_C + c4 * 4];
                acc[c4 * 4 + 0] = fmaf(xs[kk], w.x, acc[c4 * 4 + 0]);
                acc[c4 * 4 + 1] = fmaf(xs[kk], w.y, acc[c4 * 4 + 1]);
                acc[c4 * 4 + 2] = fmaf(xs[kk], w.z, acc[c4 * 4 + 2]);
                acc[c4 * 4 + 3] = fmaf(xs[kk], w.w, acc[c4 * 4 + 3]);
            }
        }
    }
    float4* ho = (float4*)(g_h + (size_t)n0 * OUT_C);
    ho[0] = make_float4(acc[0], acc[1], acc[2], acc[3]);
    ho[1] = make_float4(acc[4], acc[5], acc[6], acc[7]);
    ho[2] = make_float4(acc[8], acc[9], acc[10], acc[11]);
    ho[3] = make_float4(acc[12], acc[13], acc[14], acc[15]);
}

// ---------------------------------------------------------------------------
// Edge kernel, 4 threads per edge (quad). Lane sub = t%4 owns channels
// [sub*4, sub*4+4). The h-row gather is one LDG.128 per thread, a quad
// covering one 64B row -> 8 distinct lines per warp instruction instead
// of 32. Softmax reduces across the quad with width-4 shfl.
// ---------------------------------------------------------------------------
__global__ void edge_kernel(const int* __restrict__ ei, const float* __restrict__ eattr,
                            const float* __restrict__ eaw, const float* __restrict__ eab,
                            float* __restrict__ out, int E) {
    __shared__ __align__(16) float sw[EA_D * OUT_C];
    __shared__ __align__(16) float sb[OUT_C];
    __shared__ float sbp[16];
    __shared__ __align__(8) float2 sAB[17];
    int t = threadIdx.x;
    if (t < EA_D * OUT_C) sw[t] = eaw[t];
    if (t < OUT_C) sb[t] = eab[t];
    if (t >= 128 && t < 144) sbp[t - 128] = g_bp[t - 128];
    if (t >= 160 && t < 177) sAB[t - 160] = g_AB[t - 160];
    __syncthreads();

    int e = blockIdx.x * (blockDim.x >> 2) + (t >> 2);
    if (e >= E) return;
    int sub = t & 3;

    int row = ei[e] - 1;       // edge_index[0] - 1
    int col = ei[E + e];       // edge_index[1]

    // all 4 lanes of a quad load the full 8 attrs (same addr -> broadcast)
    const float4* ap = (const float4*)(eattr + (size_t)e * EA_D);
    float4 a0 = ap[0], a1 = ap[1];
    float av[8] = {a0.x, a0.y, a0.z, a0.w, a1.x, a1.y, a1.z, a1.w};

    // gather: one float4 = this lane's 4 channels of the h row
    float4 hva = *(const float4*)(g_h + (size_t)col * OUT_C + sub * 4);
    float hv[4] = {hva.x, hva.y, hva.z, hva.w};

    // ea GEMV for 4 channels
    float4 b4 = *(const float4*)&sb[sub * 4];
    float acc[4] = {b4.x, b4.y, b4.z, b4.w};
#pragma unroll
    for (int k = 0; k < EA_D; k++) {
        float4 w = *(const float4*)&sw[k * OUT_C + sub * 4];
        acc[0] = fmaf(av[k], w.x, acc[0]);
        acc[1] = fmaf(av[k], w.y, acc[1]);
        acc[2] = fmaf(av[k], w.z, acc[2]);
        acc[3] = fmaf(av[k], w.w, acc[3]);
    }
    float agg[4];
#pragma unroll
    for (int i = 0; i < 4; i++) agg[i] = hv[i] * acc[i];

    // scores via pwl lookup: 4-step binary search over sorted breakpoints
    float sc[4];
#pragma unroll
    for (int i = 0; i < 4; i++) {
        float tv = agg[i];
        int p = (tv >= sbp[7]) ? 8 : 0;
        p += (tv >= sbp[p + 3]) ? 4 : 0;
        p += (tv >= sbp[p + 1]) ? 2 : 0;
        p += (tv >= sbp[p]) ? 1 : 0;
        float2 ab = sAB[p];
        sc[i] = fmaf(ab.x, tv, ab.y);
    }

    // softmax over 16 channels (quad-wide reduction)
    float m = fmaxf(fmaxf(sc[0], sc[1]), fmaxf(sc[2], sc[3]));
    m = fmaxf(m, __shfl_xor_sync(0xffffffffu, m, 1, 4));
    m = fmaxf(m, __shfl_xor_sync(0xffffffffu, m, 2, 4));
    float sum = 0.0f;
#pragma unroll
    for (int i = 0; i < 4; i++) { sc[i] = __expf(sc[i] - m); sum += sc[i]; }
    sum += __shfl_xor_sync(0xffffffffu, sum, 1, 4);
    sum += __shfl_xor_sync(0xffffffffu, sum, 2, 4);
    float inv = 1.0f / sum;

    float v0 = agg[0] * sc[0] * inv;
    float v1 = agg[1] * sc[1] * inv;
    float v2 = agg[2] * sc[2] * inv;
    float v3 = agg[3] * sc[3] * inv;
    float* op = out + (size_t)row * OUT_C + sub * 4;
    asm volatile("red.global.add.v4.f32 [%0], {%1, %2, %3, %4};"
                 :: "l"(op), "f"(v0), "f"(v1), "f"(v2), "f"(v3)
                 : "memory");
}

// ---------------------------------------------------------------------------
extern "C" void kernel_launch(void* const* d_in, const int* in_sizes, int n_in,
                              void* d_out, int out_size) {
    const float* x     = (const float*)d_in[0];
    const int*   ei    = (const int*)  d_in[1];
    const float* eattr = (const float*)d_in[2];
    const float* lw    = (const float*)d_in[3];
    const float* lb    = (const float*)d_in[4];
    const float* eaw   = (const float*)d_in[5];
    const float* eab   = (const float*)d_in[6];
    const float* aw1   = (const float*)d_in[7];
    const float* ab1   = (const float*)d_in[8];
    const float* aw2   = (const float*)d_in[9];
    const float* ab2   = (const float*)d_in[10];
    float* out = (float*)d_out;

    int n = in_sizes[0] / IN_C;
    int E = in_sizes[2] / EA_D;

    h_kernel<<<(n + 255) / 256, 256>>>(x, lw, lb, out, aw1, ab1, aw2, ab2, n);
    // 256 threads = 64 edges per block
    edge_kernel<<<(E + 63) / 64, 256>>>(ei, eattr, eaw, eab, out, E);
}